// round 15
// baseline (speedup 1.0000x reference)
#include <cuda_runtime.h>
#include <cuda_fp16.h>

#define NN 100000
#define NE 1600000
#define DD 128
#define BN_EPS 1e-5f
#define NSCAN ((NN + 1023) / 1024)    // 98

// ---- scratch (static device globals; no runtime allocation) ----
__device__ int    g_degi[NN];          // zeroed at load; re-zeroed by k_gemm prologue
__device__ int    g_off[NN + 1];
__device__ int    g_offtmp[NN];
__device__ int    g_cursor[NN];
__device__ int    g_bsum[128];
__device__ int    g_tick;
__device__ int    g_srcs[NE];
__device__ uint2  g_xh[NN * 32];       // fp16 x·dinv (pre-scaled): [N][128] halfs
__device__ uint4  g_agg16[NN * 16];    // fp16 normalized aggregate [N][128]
__device__ uint2  g_bfrag[8 * 16 * 32];// mma B fragments: [kstep][ntile][lane]
__device__ float2 g_sc2[64];           // BN scale per col pair
__device__ float2 g_sh2[64];           // BN shift per col pair

// ---------------- prep ----------------

// 4 edges per thread (int4): independent atomic chains
__global__ void k_count(const int4* __restrict__ dst4) {
    int e = blockIdx.x * blockDim.x + threadIdx.x;
    if (e < NE / 4) {
        int4 d = __ldg(&dst4[e]);
        atomicAdd(&g_degi[d.x], 1);
        atomicAdd(&g_degi[d.y], 1);
        atomicAdd(&g_degi[d.z], 1);
        atomicAdd(&g_degi[d.w], 1);
    }
}

__global__ void k_scan1() {
    __shared__ int wsum[32];
    int tid = threadIdx.x;
    int gid = blockIdx.x * 1024 + tid;
    int v = (gid < NN) ? g_degi[gid] : 0;
    int x = v;
    #pragma unroll
    for (int o = 1; o < 32; o <<= 1) {
        int t = __shfl_up_sync(0xffffffffu, x, o);
        if ((tid & 31) >= o) x += t;
    }
    if ((tid & 31) == 31) wsum[tid >> 5] = x;
    __syncthreads();
    if (tid < 32) {
        int s = wsum[tid];
        #pragma unroll
        for (int o = 1; o < 32; o <<= 1) {
            int t = __shfl_up_sync(0xffffffffu, s, o);
            if (tid >= o) s += t;
        }
        wsum[tid] = s;
    }
    __syncthreads();
    int add  = (tid >= 32) ? wsum[(tid >> 5) - 1] : 0;
    int incl = x + add;
    if (gid < NN) g_offtmp[gid] = incl - v;
    if (tid == 1023) g_bsum[blockIdx.x] = incl;
}

// merged: scan finalize (offsets/cursors) + FULL fp16 x·dinv conversion (pure
// streaming, no atomics in this kernel) + bfrag + BN tables + tick reset.
// Grid: NN*16 threads (6250 blocks), 2 xh granules per thread.
__global__ void k_scan23x(const float4* __restrict__ x4, const float* __restrict__ W,
                          const float* __restrict__ bia, const float* __restrict__ gam,
                          const float* __restrict__ bet, const float* __restrict__ rme,
                          const float* __restrict__ rva) {
    __shared__ int pre[NSCAN];
    __shared__ int wtot[4];
    int tid = threadIdx.x, lane = tid & 31, w = tid >> 5;
    int idx = blockIdx.x * blockDim.x + tid;

    if (tid < 128) {
        int v = (tid < NSCAN) ? g_bsum[tid] : 0;
        int x = v;
        #pragma unroll
        for (int o = 1; o < 32; o <<= 1) {
            int t = __shfl_up_sync(0xffffffffu, x, o);
            if (lane >= o) x += t;
        }
        if (lane == 31) wtot[w] = x;
        __syncwarp();
    }
    __syncthreads();
    if (tid == 0) {
        int run = 0;
        #pragma unroll
        for (int i = 0; i < 4; i++) { int q = wtot[i]; wtot[i] = run; run += q; }
    }
    __syncthreads();
    if (tid < 128) {
        int v = (tid < NSCAN) ? g_bsum[tid] : 0;
        int x = v;
        #pragma unroll
        for (int o = 1; o < 32; o <<= 1) {
            int t = __shfl_up_sync(0xffffffffu, x, o);
            if (lane >= o) x += t;
        }
        if (tid < NSCAN) pre[tid] = x - v + wtot[w];
    }
    __syncthreads();

    // offsets / cursors (threads with idx < NN)
    if (idx < NN) {
        int off = g_offtmp[idx] + pre[idx >> 10];
        g_off[idx]    = off;
        g_cursor[idx] = off;
    }
    if (blockIdx.x == 0 && tid == 0) {
        g_off[NN] = NE;
        g_tick = 0;
    }

    // fp16 pre-scaled conversion: dinv computed inline from g_degi (final after count)
    if (idx < NN * 16) {
        #pragma unroll
        for (int h = 0; h < 2; h++) {
            int gi = idx + h * (NN * 16);
            int node = gi >> 5;
            float di = rsqrtf((float)__ldg(&g_degi[node]) + 1.0f);
            float4 v = __ldg(&x4[gi]);
            __half2 h0 = __floats2half2_rn(v.x * di, v.y * di);
            __half2 h1 = __floats2half2_rn(v.z * di, v.w * di);
            uint2 u;
            u.x = *(unsigned int*)&h0;
            u.y = *(unsigned int*)&h1;
            g_xh[gi] = u;
        }
    }

    if (idx < 8 * 16 * 32) {
        // B fragment for mma.m16n8k16 (col-major B): B[k][n] = W[n][k]
        int fl = idx & 31, nt = (idx >> 5) & 15, ks = idx >> 9;
        int n  = nt * 8 + (fl >> 2);
        int k0 = ks * 16 + (fl & 3) * 2;
        const float* wr = W + n * DD;
        __half2 b0 = __floats2half2_rn(wr[k0],     wr[k0 + 1]);
        __half2 b1 = __floats2half2_rn(wr[k0 + 8], wr[k0 + 9]);
        uint2 u;
        u.x = *(unsigned int*)&b0;
        u.y = *(unsigned int*)&b1;
        g_bfrag[idx] = u;
    }
    if (idx < 64) {
        float2 gg = ((const float2*)gam)[idx];
        float2 vv = ((const float2*)rva)[idx];
        float2 bb = ((const float2*)bia)[idx];
        float2 mm = ((const float2*)rme)[idx];
        float2 be = ((const float2*)bet)[idx];
        float2 sc, sh;
        sc.x = gg.x * rsqrtf(vv.x + BN_EPS);
        sc.y = gg.y * rsqrtf(vv.y + BN_EPS);
        sh.x = (bb.x - mm.x) * sc.x + be.x;
        sh.y = (bb.y - mm.y) * sc.y + be.y;
        g_sc2[idx] = sc;
        g_sh2[idx] = sh;
    }
}

// ---------------- bin only: CSR fill, 2 independent chains/thread ----------------
__global__ void k_bin(const int* __restrict__ src, const int* __restrict__ dst) {
    int e = blockIdx.x * blockDim.x + threadIdx.x;
    if (e < NE / 2) {
        int s0 = __ldg(&src[e]);
        int d0 = __ldg(&dst[e]);
        int s1 = __ldg(&src[e + NE / 2]);
        int d1 = __ldg(&dst[e + NE / 2]);
        int p0 = atomicAdd(&g_cursor[d0], 1);
        int p1 = atomicAdd(&g_cursor[d1], 1);
        g_srcs[p0] = s0;
        g_srcs[p1] = s1;
    }
}

// ---------------- gather: one warp per node, cross-node pipeline ----------------
#define GATHER_BLOCKS 1184
#define GATHER_WPB    8

__global__ void __launch_bounds__(256) k_gather() {
    int lane = threadIdx.x & 31;
    int gw   = blockIdx.x * GATHER_WPB + (threadIdx.x >> 5);
    const int nwarps = GATHER_BLOCKS * GATHER_WPB;

    int node = gw;
    int beg = 0, end = 0;
    if (node < NN) {
        beg = __ldg(&g_off[node]);
        end = __ldg(&g_off[node + 1]);
    }
    int s0 = 0;
    if (node < NN && beg + lane < end) s0 = __ldg(&g_srcs[beg + lane]);

    while (node < NN) {
        int nodeN = node + nwarps;
        int begN = 0, endN = 0;
        if (nodeN < NN) {
            begN = __ldg(&g_off[nodeN]);
            endN = __ldg(&g_off[nodeN + 1]);
        }

        float di = rsqrtf((float)(end - beg) + 1.0f);   // deg from CSR bounds
        uint2 hs = __ldg(&g_xh[node * 32 + lane]);      // self term (pre-scaled)
        float2 t0 = __half22float2(*(__half2*)&hs.x);
        float2 t1 = __half22float2(*(__half2*)&hs.y);
        float4 acc = make_float4(t0.x, t0.y, t1.x, t1.y);

        int n1 = end - beg; if (n1 > 32) n1 = 32;
        #pragma unroll 8
        for (int jj = 0; jj < n1; jj++) {
            int s = __shfl_sync(0xffffffffu, s0, jj);
            uint2 hv = __ldg(&g_xh[s * 32 + lane]);
            float2 f0 = __half22float2(*(__half2*)&hv.x);
            float2 f1 = __half22float2(*(__half2*)&hv.y);
            acc.x += f0.x; acc.y += f0.y;
            acc.z += f1.x; acc.w += f1.y;
        }
        for (int base = beg + 32; base < end; base += 32) {
            int n = end - base; if (n > 32) n = 32;
            int sv = (lane < n) ? __ldg(&g_srcs[base + lane]) : 0;
            #pragma unroll 8
            for (int jj = 0; jj < n; jj++) {
                int s = __shfl_sync(0xffffffffu, sv, jj);
                uint2 hv = __ldg(&g_xh[s * 32 + lane]);
                float2 f0 = __half22float2(*(__half2*)&hv.x);
                float2 f1 = __half22float2(*(__half2*)&hv.y);
                acc.x += f0.x; acc.y += f0.y;
                acc.z += f1.x; acc.w += f1.y;
            }
        }

        int sN = 0;
        if (nodeN < NN && begN + lane < endN) sN = __ldg(&g_srcs[begN + lane]);

        acc.x *= di; acc.y *= di; acc.z *= di; acc.w *= di;
        __half2 h0 = __floats2half2_rn(acc.x, acc.y);
        __half2 h1 = __floats2half2_rn(acc.z, acc.w);
        uint2 u;
        u.x = *(unsigned int*)&h0;
        u.y = *(unsigned int*)&h1;
        ((uint2*)g_agg16)[node * 32 + lane] = u;

        node = nodeN; beg = begN; end = endN; s0 = sN;
    }
}

// ---------------- tensor-core GEMM (R8 version) + BN + ReLU + res + ReLU ----
#define CROWS 128
#define NCH   ((NN + CROWS - 1) / CROWS)   // 782
#define GGRID 296

__global__ void __launch_bounds__(256, 2) k_gemm(
    const float2* __restrict__ x2, float2* __restrict__ out2)
{
    __shared__ __align__(16) char sAraw[CROWS * 256];   // 32KB fp16 A chunk, swizzled
    __shared__ int s_chunk;

    int tid = threadIdx.x, lane = tid & 31, w = tid >> 5;

    // zero g_degi for next replay's k_count (stream-ordered)
    for (int i = blockIdx.x * blockDim.x + tid; i < NN; i += gridDim.x * blockDim.x)
        g_degi[i] = 0;

    unsigned int sA;
    { unsigned long long t;
      asm("cvta.to.shared.u64 %0, %1;" : "=l"(t) : "l"(sAraw));
      sA = (unsigned int)t; }

    int rloc  = w * 16 + ((lane >> 3) & 1) * 8 + (lane & 7);
    int gsel  = lane >> 4;

    const uint4* aggv = g_agg16;

    while (true) {
        if (tid == 0) s_chunk = atomicAdd(&g_tick, 1);
        __syncthreads();
        int chunk = s_chunk;
        if (chunk >= NCH) break;
        int row0 = chunk * CROWS;

        #pragma unroll
        for (int ii = 0; ii < 8; ii++) {
            int i = tid + ii * 256;
            int r = i >> 4, c = i & 15;
            int grow = row0 + r;
            uint4 v = (grow < NN) ? __ldg(&aggv[grow * 16 + c])
                                  : make_uint4(0u, 0u, 0u, 0u);
            int sw = (c & 8) | ((c ^ r) & 7);
            *(uint4*)(sAraw + r * 256 + sw * 16) = v;
        }
        __syncthreads();

        float acc[16][4];
        #pragma unroll
        for (int nt = 0; nt < 16; nt++)
            #pragma unroll
            for (int q = 0; q < 4; q++) acc[nt][q] = 0.0f;

        #pragma unroll
        for (int ks = 0; ks < 8; ks++) {
            int c = ks * 2 + gsel;
            int sw = (c & 8) | ((c ^ rloc) & 7);
            unsigned int addr = sA + rloc * 256 + sw * 16;
            unsigned int a0, a1, a2, a3;
            asm volatile("ldmatrix.sync.aligned.m8n8.x4.shared.b16 {%0,%1,%2,%3}, [%4];"
                         : "=r"(a0), "=r"(a1), "=r"(a2), "=r"(a3) : "r"(addr));
            #pragma unroll
            for (int nt = 0; nt < 16; nt++) {
                uint2 b = __ldg(&g_bfrag[(ks * 16 + nt) * 32 + lane]);
                asm volatile(
                    "mma.sync.aligned.m16n8k16.row.col.f32.f16.f16.f32 "
                    "{%0,%1,%2,%3}, {%4,%5,%6,%7}, {%8,%9}, {%0,%1,%2,%3};"
                    : "+f"(acc[nt][0]), "+f"(acc[nt][1]), "+f"(acc[nt][2]), "+f"(acc[nt][3])
                    : "r"(a0), "r"(a1), "r"(a2), "r"(a3), "r"(b.x), "r"(b.y));
            }
        }

        int rA = row0 + w * 16 + (lane >> 2);
        int rB = rA + 8;
        int ci = lane & 3;
        #pragma unroll
        for (int nt = 0; nt < 16; nt++) {
            int cp = nt * 4 + ci;
            float2 sc = __ldg(&g_sc2[cp]);
            float2 sh = __ldg(&g_sh2[cp]);
            if (rA < NN) {
                float2 xv = __ldg(&x2[rA * 64 + cp]);
                float2 o;
                o.x = fmaxf(fmaxf(acc[nt][0] * sc.x + sh.x, 0.f) + xv.x, 0.f);
                o.y = fmaxf(fmaxf(acc[nt][1] * sc.y + sh.y, 0.f) + xv.y, 0.f);
                out2[rA * 64 + cp] = o;
            }
            if (rB < NN) {
                float2 xv = __ldg(&x2[rB * 64 + cp]);
                float2 o;
                o.x = fmaxf(fmaxf(acc[nt][2] * sc.x + sh.x, 0.f) + xv.x, 0.f);
                o.y = fmaxf(fmaxf(acc[nt][3] * sc.y + sh.y, 0.f) + xv.y, 0.f);
                out2[rB * 64 + cp] = o;
            }
        }
        __syncthreads();
    }
}

// ---------------- launch ----------------

extern "C" void kernel_launch(void* const* d_in, const int* in_sizes, int n_in,
                              void* d_out, int out_size) {
    const float* x     = (const float*)d_in[0];
    const int*   eidx  = (const int*)  d_in[1];   // [2][E]: row0 = src, row1 = dst
    const float* W     = (const float*)d_in[2];
    const float* b     = (const float*)d_in[3];
    const float* gamma = (const float*)d_in[4];
    const float* beta  = (const float*)d_in[5];
    const float* rmean = (const float*)d_in[6];
    const float* rvar  = (const float*)d_in[7];
    float* out = (float*)d_out;

    const int* src = eidx;
    const int* dst = eidx + NE;

    k_count<<<(NE / 4 + 255) / 256, 256>>>((const int4*)dst);
    k_scan1<<<NSCAN, 1024>>>();
    k_scan23x<<<(NN * 16 + 255) / 256, 256>>>((const float4*)x, W,
                                              b, gamma, beta, rmean, rvar);
    k_bin<<<(NE / 2 + 255) / 256, 256>>>(src, dst);
    k_gather<<<GATHER_BLOCKS, 256>>>();
    k_gemm<<<GGRID, 256>>>((const float2*)x, (float2*)out);
}

// round 16
// speedup vs baseline: 1.0466x; 1.0466x over previous
#include <cuda_runtime.h>
#include <cuda_fp16.h>

#define NN 100000
#define NE 1600000
#define DD 128
#define BN_EPS 1e-5f
#define NSCAN ((NN + 1023) / 1024)    // 98

// ---- scratch (static device globals; no runtime allocation) ----
__device__ int    g_degi[NN];          // zeroed at load; re-zeroed by k_gemm prologue
__device__ int    g_off[NN + 1];
__device__ int    g_offtmp[NN];
__device__ int    g_cursor[NN];
__device__ int    g_bsum[128];
__device__ int    g_tick;
__device__ int    g_srcs[NE];
__device__ uint2  g_xh[NN * 32];       // fp16 x·dinv (pre-scaled): [N][128] halfs
__device__ uint4  g_agg16[NN * 16];    // fp16 normalized aggregate [N][128]
__device__ uint2  g_bfrag[8 * 16 * 32];// mma B fragments: [kstep][ntile][lane]
__device__ float2 g_sc2[64];           // BN scale per col pair
__device__ float2 g_sh2[64];           // BN shift per col pair

// ---------------- prep ----------------

// 4 edges per thread (int4): independent atomic chains
__global__ void k_count(const int4* __restrict__ dst4) {
    int e = blockIdx.x * blockDim.x + threadIdx.x;
    if (e < NE / 4) {
        int4 d = __ldg(&dst4[e]);
        atomicAdd(&g_degi[d.x], 1);
        atomicAdd(&g_degi[d.y], 1);
        atomicAdd(&g_degi[d.z], 1);
        atomicAdd(&g_degi[d.w], 1);
    }
}

__global__ void k_scan1() {
    __shared__ int wsum[32];
    int tid = threadIdx.x;
    int gid = blockIdx.x * 1024 + tid;
    int v = (gid < NN) ? g_degi[gid] : 0;
    int x = v;
    #pragma unroll
    for (int o = 1; o < 32; o <<= 1) {
        int t = __shfl_up_sync(0xffffffffu, x, o);
        if ((tid & 31) >= o) x += t;
    }
    if ((tid & 31) == 31) wsum[tid >> 5] = x;
    __syncthreads();
    if (tid < 32) {
        int s = wsum[tid];
        #pragma unroll
        for (int o = 1; o < 32; o <<= 1) {
            int t = __shfl_up_sync(0xffffffffu, s, o);
            if (tid >= o) s += t;
        }
        wsum[tid] = s;
    }
    __syncthreads();
    int add  = (tid >= 32) ? wsum[(tid >> 5) - 1] : 0;
    int incl = x + add;
    if (gid < NN) g_offtmp[gid] = incl - v;
    if (tid == 1023) g_bsum[blockIdx.x] = incl;
}

// scan finalize: offsets + cursors + tick (small grid — conversion moved out)
__global__ void k_scan23() {
    __shared__ int pre[NSCAN];
    __shared__ int wtot[4];
    int tid = threadIdx.x, lane = tid & 31, w = tid >> 5;

    if (tid < 128) {
        int v = (tid < NSCAN) ? g_bsum[tid] : 0;
        int x = v;
        #pragma unroll
        for (int o = 1; o < 32; o <<= 1) {
            int t = __shfl_up_sync(0xffffffffu, x, o);
            if (lane >= o) x += t;
        }
        if (lane == 31) wtot[w] = x;
        __syncwarp();
    }
    __syncthreads();
    if (tid == 0) {
        int run = 0;
        #pragma unroll
        for (int i = 0; i < 4; i++) { int q = wtot[i]; wtot[i] = run; run += q; }
    }
    __syncthreads();
    if (tid < 128) {
        int v = (tid < NSCAN) ? g_bsum[tid] : 0;
        int x = v;
        #pragma unroll
        for (int o = 1; o < 32; o <<= 1) {
            int t = __shfl_up_sync(0xffffffffu, x, o);
            if (lane >= o) x += t;
        }
        if (tid < NSCAN) pre[tid] = x - v + wtot[w];
    }
    __syncthreads();

    int i = blockIdx.x * blockDim.x + tid;
    if (i < NN) {
        int off = g_offtmp[i] + pre[i >> 10];
        g_off[i]    = off;
        g_cursor[i] = off;
    }
    if (blockIdx.x == 0 && tid == 0) {
        g_off[NN] = NE;
        g_tick = 0;
    }
}

// forked stream: fp16 x·dinv conversion (needs only g_degi, final after count)
// + bfrag + BN tables. Pure streaming; runs concurrent with scan/bin chain.
__global__ void k_xconv(const float4* __restrict__ x4, const float* __restrict__ W,
                        const float* __restrict__ bia, const float* __restrict__ gam,
                        const float* __restrict__ bet, const float* __restrict__ rme,
                        const float* __restrict__ rva) {
    int idx = blockIdx.x * blockDim.x + threadIdx.x;

    if (idx < NN * 16) {
        #pragma unroll
        for (int h = 0; h < 2; h++) {
            int gi = idx + h * (NN * 16);
            int node = gi >> 5;
            float di = rsqrtf((float)__ldg(&g_degi[node]) + 1.0f);
            float4 v = __ldg(&x4[gi]);
            __half2 h0 = __floats2half2_rn(v.x * di, v.y * di);
            __half2 h1 = __floats2half2_rn(v.z * di, v.w * di);
            uint2 u;
            u.x = *(unsigned int*)&h0;
            u.y = *(unsigned int*)&h1;
            g_xh[gi] = u;
        }
    }
    if (idx < 8 * 16 * 32) {
        // B fragment for mma.m16n8k16 (col-major B): B[k][n] = W[n][k]
        int fl = idx & 31, nt = (idx >> 5) & 15, ks = idx >> 9;
        int n  = nt * 8 + (fl >> 2);
        int k0 = ks * 16 + (fl & 3) * 2;
        const float* wr = W + n * DD;
        __half2 b0 = __floats2half2_rn(wr[k0],     wr[k0 + 1]);
        __half2 b1 = __floats2half2_rn(wr[k0 + 8], wr[k0 + 9]);
        uint2 u;
        u.x = *(unsigned int*)&b0;
        u.y = *(unsigned int*)&b1;
        g_bfrag[idx] = u;
    }
    if (idx < 64) {
        float2 gg = ((const float2*)gam)[idx];
        float2 vv = ((const float2*)rva)[idx];
        float2 bb = ((const float2*)bia)[idx];
        float2 mm = ((const float2*)rme)[idx];
        float2 be = ((const float2*)bet)[idx];
        float2 sc, sh;
        sc.x = gg.x * rsqrtf(vv.x + BN_EPS);
        sc.y = gg.y * rsqrtf(vv.y + BN_EPS);
        sh.x = (bb.x - mm.x) * sc.x + be.x;
        sh.y = (bb.y - mm.y) * sc.y + be.y;
        g_sc2[idx] = sc;
        g_sh2[idx] = sh;
    }
}

// ---------------- bin: CSR fill, 2 independent chains/thread ----------------
__global__ void k_bin(const int* __restrict__ src, const int* __restrict__ dst) {
    int e = blockIdx.x * blockDim.x + threadIdx.x;
    if (e < NE / 2) {
        int s0 = __ldg(&src[e]);
        int d0 = __ldg(&dst[e]);
        int s1 = __ldg(&src[e + NE / 2]);
        int d1 = __ldg(&dst[e + NE / 2]);
        int p0 = atomicAdd(&g_cursor[d0], 1);
        int p1 = atomicAdd(&g_cursor[d1], 1);
        g_srcs[p0] = s0;
        g_srcs[p1] = s1;
    }
}

// ---------------- gather: one warp per node, cross-node pipeline ----------------
#define GATHER_BLOCKS 1184
#define GATHER_WPB    8

__global__ void __launch_bounds__(256) k_gather() {
    int lane = threadIdx.x & 31;
    int gw   = blockIdx.x * GATHER_WPB + (threadIdx.x >> 5);
    const int nwarps = GATHER_BLOCKS * GATHER_WPB;

    int node = gw;
    int beg = 0, end = 0;
    if (node < NN) {
        beg = __ldg(&g_off[node]);
        end = __ldg(&g_off[node + 1]);
    }
    int s0 = 0;
    if (node < NN && beg + lane < end) s0 = __ldg(&g_srcs[beg + lane]);

    while (node < NN) {
        int nodeN = node + nwarps;
        int begN = 0, endN = 0;
        if (nodeN < NN) {
            begN = __ldg(&g_off[nodeN]);
            endN = __ldg(&g_off[nodeN + 1]);
        }

        float di = rsqrtf((float)(end - beg) + 1.0f);   // deg from CSR bounds
        uint2 hs = __ldg(&g_xh[node * 32 + lane]);      // self term (pre-scaled)
        float2 t0 = __half22float2(*(__half2*)&hs.x);
        float2 t1 = __half22float2(*(__half2*)&hs.y);
        float4 acc = make_float4(t0.x, t0.y, t1.x, t1.y);

        int n1 = end - beg; if (n1 > 32) n1 = 32;
        #pragma unroll 8
        for (int jj = 0; jj < n1; jj++) {
            int s = __shfl_sync(0xffffffffu, s0, jj);
            uint2 hv = __ldg(&g_xh[s * 32 + lane]);
            float2 f0 = __half22float2(*(__half2*)&hv.x);
            float2 f1 = __half22float2(*(__half2*)&hv.y);
            acc.x += f0.x; acc.y += f0.y;
            acc.z += f1.x; acc.w += f1.y;
        }
        for (int base = beg + 32; base < end; base += 32) {
            int n = end - base; if (n > 32) n = 32;
            int sv = (lane < n) ? __ldg(&g_srcs[base + lane]) : 0;
            #pragma unroll 8
            for (int jj = 0; jj < n; jj++) {
                int s = __shfl_sync(0xffffffffu, sv, jj);
                uint2 hv = __ldg(&g_xh[s * 32 + lane]);
                float2 f0 = __half22float2(*(__half2*)&hv.x);
                float2 f1 = __half22float2(*(__half2*)&hv.y);
                acc.x += f0.x; acc.y += f0.y;
                acc.z += f1.x; acc.w += f1.y;
            }
        }

        int sN = 0;
        if (nodeN < NN && begN + lane < endN) sN = __ldg(&g_srcs[begN + lane]);

        acc.x *= di; acc.y *= di; acc.z *= di; acc.w *= di;
        __half2 h0 = __floats2half2_rn(acc.x, acc.y);
        __half2 h1 = __floats2half2_rn(acc.z, acc.w);
        uint2 u;
        u.x = *(unsigned int*)&h0;
        u.y = *(unsigned int*)&h1;
        ((uint2*)g_agg16)[node * 32 + lane] = u;

        node = nodeN; beg = begN; end = endN; s0 = sN;
    }
}

// ---------------- tensor-core GEMM (R8 version) + BN + ReLU + res + ReLU ----
#define CROWS 128
#define NCH   ((NN + CROWS - 1) / CROWS)   // 782
#define GGRID 296

__global__ void __launch_bounds__(256, 2) k_gemm(
    const float2* __restrict__ x2, float2* __restrict__ out2)
{
    __shared__ __align__(16) char sAraw[CROWS * 256];   // 32KB fp16 A chunk, swizzled
    __shared__ int s_chunk;

    int tid = threadIdx.x, lane = tid & 31, w = tid >> 5;

    // zero g_degi for next replay's k_count (stream-ordered)
    for (int i = blockIdx.x * blockDim.x + tid; i < NN; i += gridDim.x * blockDim.x)
        g_degi[i] = 0;

    unsigned int sA;
    { unsigned long long t;
      asm("cvta.to.shared.u64 %0, %1;" : "=l"(t) : "l"(sAraw));
      sA = (unsigned int)t; }

    int rloc  = w * 16 + ((lane >> 3) & 1) * 8 + (lane & 7);
    int gsel  = lane >> 4;

    const uint4* aggv = g_agg16;

    while (true) {
        if (tid == 0) s_chunk = atomicAdd(&g_tick, 1);
        __syncthreads();
        int chunk = s_chunk;
        if (chunk >= NCH) break;
        int row0 = chunk * CROWS;

        #pragma unroll
        for (int ii = 0; ii < 8; ii++) {
            int i = tid + ii * 256;
            int r = i >> 4, c = i & 15;
            int grow = row0 + r;
            uint4 v = (grow < NN) ? __ldg(&aggv[grow * 16 + c])
                                  : make_uint4(0u, 0u, 0u, 0u);
            int sw = (c & 8) | ((c ^ r) & 7);
            *(uint4*)(sAraw + r * 256 + sw * 16) = v;
        }
        __syncthreads();

        float acc[16][4];
        #pragma unroll
        for (int nt = 0; nt < 16; nt++)
            #pragma unroll
            for (int q = 0; q < 4; q++) acc[nt][q] = 0.0f;

        #pragma unroll
        for (int ks = 0; ks < 8; ks++) {
            int c = ks * 2 + gsel;
            int sw = (c & 8) | ((c ^ rloc) & 7);
            unsigned int addr = sA + rloc * 256 + sw * 16;
            unsigned int a0, a1, a2, a3;
            asm volatile("ldmatrix.sync.aligned.m8n8.x4.shared.b16 {%0,%1,%2,%3}, [%4];"
                         : "=r"(a0), "=r"(a1), "=r"(a2), "=r"(a3) : "r"(addr));
            #pragma unroll
            for (int nt = 0; nt < 16; nt++) {
                uint2 b = __ldg(&g_bfrag[(ks * 16 + nt) * 32 + lane]);
                asm volatile(
                    "mma.sync.aligned.m16n8k16.row.col.f32.f16.f16.f32 "
                    "{%0,%1,%2,%3}, {%4,%5,%6,%7}, {%8,%9}, {%0,%1,%2,%3};"
                    : "+f"(acc[nt][0]), "+f"(acc[nt][1]), "+f"(acc[nt][2]), "+f"(acc[nt][3])
                    : "r"(a0), "r"(a1), "r"(a2), "r"(a3), "r"(b.x), "r"(b.y));
            }
        }

        int rA = row0 + w * 16 + (lane >> 2);
        int rB = rA + 8;
        int ci = lane & 3;
        #pragma unroll
        for (int nt = 0; nt < 16; nt++) {
            int cp = nt * 4 + ci;
            float2 sc = __ldg(&g_sc2[cp]);
            float2 sh = __ldg(&g_sh2[cp]);
            if (rA < NN) {
                float2 xv = __ldg(&x2[rA * 64 + cp]);
                float2 o;
                o.x = fmaxf(fmaxf(acc[nt][0] * sc.x + sh.x, 0.f) + xv.x, 0.f);
                o.y = fmaxf(fmaxf(acc[nt][1] * sc.y + sh.y, 0.f) + xv.y, 0.f);
                out2[rA * 64 + cp] = o;
            }
            if (rB < NN) {
                float2 xv = __ldg(&x2[rB * 64 + cp]);
                float2 o;
                o.x = fmaxf(fmaxf(acc[nt][2] * sc.x + sh.x, 0.f) + xv.x, 0.f);
                o.y = fmaxf(fmaxf(acc[nt][3] * sc.y + sh.y, 0.f) + xv.y, 0.f);
                out2[rB * 64 + cp] = o;
            }
        }
        __syncthreads();
    }
}

// ---------------- launch: forked-stream DAG ----------------

extern "C" void kernel_launch(void* const* d_in, const int* in_sizes, int n_in,
                              void* d_out, int out_size) {
    const float* x     = (const float*)d_in[0];
    const int*   eidx  = (const int*)  d_in[1];   // [2][E]: row0 = src, row1 = dst
    const float* W     = (const float*)d_in[2];
    const float* b     = (const float*)d_in[3];
    const float* gamma = (const float*)d_in[4];
    const float* beta  = (const float*)d_in[5];
    const float* rmean = (const float*)d_in[6];
    const float* rvar  = (const float*)d_in[7];
    float* out = (float*)d_out;

    const int* src = eidx;
    const int* dst = eidx + NE;

    static cudaStream_t s2;
    static cudaEvent_t  evFork, evJoin;
    static int init = 0;
    if (!init) {
        cudaStreamCreateWithFlags(&s2, cudaStreamNonBlocking);
        cudaEventCreateWithFlags(&evFork, cudaEventDisableTiming);
        cudaEventCreateWithFlags(&evJoin, cudaEventDisableTiming);
        init = 1;
    }

    // main chain: count -> scan -> bin
    k_count<<<(NE / 4 + 255) / 256, 256>>>((const int4*)dst);

    // fork: conversion stream (depends only on count)
    cudaEventRecord(evFork, 0);
    cudaStreamWaitEvent(s2, evFork, 0);
    k_xconv<<<(NN * 16 + 255) / 256, 256, 0, s2>>>((const float4*)x, W,
                                                   b, gamma, beta, rmean, rvar);
    cudaEventRecord(evJoin, s2);

    k_scan1<<<NSCAN, 1024>>>();
    k_scan23<<<(NN + 255) / 256, 256>>>();
    k_bin<<<(NE / 2 + 255) / 256, 256>>>(src, dst);

    // join: gather needs xh (s2) + CSR (stream 0)
    cudaStreamWaitEvent(0, evJoin, 0);
    k_gather<<<GATHER_BLOCKS, 256>>>();
    k_gemm<<<GGRID, 256>>>((const float2*)x, (float2*)out);
}